// round 2
// baseline (speedup 1.0000x reference)
#include <cuda_runtime.h>

#define HH 1024
#define WW 1024
#define NPTS 128
#define WPR 32            // 32-bit words per row (1024/32)
#define SENTINEL_D 2048   // > max real 1D distance (1023); squared stays in int range

// Scratch: bitmap stored COLUMN-MAJOR over word-columns: g_bits[wc*HH + r]
// so the per-point row sweep in search_kernel is coalesced.
__device__ unsigned int g_bits[WPR * HH];
__device__ int g_on[NPTS];
__device__ int g_off[NPTS];

// ---------------------------------------------------------------------------
// Kernel 1: bitpack the float map into 32-bit words via warp ballot.
// Warp gw handles row r = gw>>5, word-col wc = gw&31; lane l reads col wc*32+l.
// Fully coalesced 128B reads per warp.
// ---------------------------------------------------------------------------
__global__ void bitpack_kernel(const float* __restrict__ hd) {
    int gw   = (blockIdx.x * blockDim.x + threadIdx.x) >> 5;
    int lane = threadIdx.x & 31;
    int r  = gw >> 5;
    int wc = gw & 31;
    float v = hd[r * WW + (wc << 5) + lane];
    unsigned int word = __ballot_sync(0xFFFFFFFFu, v != 0.0f);
    if (lane == 0) g_bits[wc * HH + r] = word;
}

// Nearest set-bit distance from query column q (= wc0*32+bit0) to any set bit
// in word m at word index w. Returns large sentinel if m == 0.
__device__ __forceinline__ int nearest_in_word(unsigned int m, int w, int wc0, int bit0) {
    if (m == 0u) return SENTINEL_D;
    if (w == wc0) {
        unsigned int maskLE = (bit0 == 31) ? 0xFFFFFFFFu : ((2u << bit0) - 1u);
        unsigned int lo = m & maskLE;        // bits at or below q
        unsigned int hi = m & ~maskLE;       // bits above q
        int d = SENTINEL_D;
        if (lo) d = bit0 - (31 - __clz(lo));
        if (hi) { int d2 = (__ffs(hi) - 1) - bit0; d = min(d, d2); }
        return d;
    } else if (w > wc0) {
        return (w << 5) + (__ffs(m) - 1) - ((wc0 << 5) + bit0);
    } else {
        return ((wc0 << 5) + bit0) - ((w << 5) + (31 - __clz(m)));
    }
}

// ---------------------------------------------------------------------------
// Kernel 2: per-point separable search.
// Block n handles point n. Thread handles rows tid, tid+256, ... (4 rows).
// For each row: ring-expanding search outward from pc's word for the nearest
// on bit and nearest off bit (inverted word). Combine with (r-pr)^2, block-
// reduce the min. Integer-exact, no atomics.
// ---------------------------------------------------------------------------
__global__ void search_kernel(const int* __restrict__ pred) {
    int n  = blockIdx.x;
    int pr = pred[2 * n];       // component 0: compared against rows in d2
    int pc = pred[2 * n + 1];   // component 1: compared against cols in d2
    int tid = threadIdx.x;

    int wc0  = pc >> 5;
    int bit0 = pc & 31;
    int q32  = (wc0 << 5) + bit0;

    int best_on  = 0x7F000000;
    int best_off = 0x7F000000;

    for (int r = tid; r < HH; r += 256) {
        int dr  = r - pr;
        int dr2 = dr * dr;
        if (dr2 >= best_on && dr2 >= best_off) continue;  // cannot improve either

        int don = SENTINEL_D, doff = SENTINEL_D;
        #pragma unroll 1
        for (int k = 0; k < WPR + 1; k++) {
            int wr = wc0 + k;
            int wl = wc0 - k;
            if (wr < WPR) {
                unsigned int m = g_bits[wr * HH + r];
                don  = min(don,  nearest_in_word(m,  wr, wc0, bit0));
                doff = min(doff, nearest_in_word(~m, wr, wc0, bit0));
            }
            if (k > 0 && wl >= 0) {
                unsigned int m = g_bits[wl * HH + r];
                don  = min(don,  nearest_in_word(m,  wl, wc0, bit0));
                doff = min(doff, nearest_in_word(~m, wl, wc0, bit0));
            }
            // lower bound on distances in the NEXT ring
            int cminR = (wr + 1 < WPR) ? ((wr + 1) << 5) - q32        : SENTINEL_D;
            int cminL = (wl - 1 >= 0)  ? q32 - (((wl - 1) << 5) + 31) : SENTINEL_D;
            int nextmin = min(cminR, cminL);
            if (don <= nextmin && doff <= nextmin) break;
        }
        don  = min(don,  SENTINEL_D);
        doff = min(doff, SENTINEL_D);
        best_on  = min(best_on,  dr2 + don * don);
        best_off = min(best_off, dr2 + doff * doff);
    }

    __shared__ int s_on[256];
    __shared__ int s_off[256];
    s_on[tid]  = best_on;
    s_off[tid] = best_off;
    __syncthreads();
    #pragma unroll
    for (int s = 128; s > 0; s >>= 1) {
        if (tid < s) {
            s_on[tid]  = min(s_on[tid],  s_on[tid + s]);
            s_off[tid] = min(s_off[tid], s_off[tid + s]);
        }
        __syncthreads();
    }
    if (tid == 0) {
        g_on[n]  = s_on[0];
        g_off[n] = s_off[0];
    }
}

// ---------------------------------------------------------------------------
// Kernel 3: per-point loss + mean.
// Replicates the reference's neighbor lookup EXACTLY: it indexes
// hd_map[py-1..py, px-1..px] where px=pred[:,0], py=pred[:,1] (roles swapped
// vs the distance computation). JAX clamps OOB indices, so we clamp too.
// ---------------------------------------------------------------------------
__global__ void finalize_kernel(const float* __restrict__ hd,
                                const int* __restrict__ pred,
                                float* __restrict__ out) {
    int n = threadIdx.x;   // 128 threads
    int px = pred[2 * n];
    int py = pred[2 * n + 1];
    bool outside_frame = (px < 0) || (px > HH) || (py < 0) || (py > WW);

    float loss = 0.0f;
    if (!outside_frame) {
        int r0 = min(max(py - 1, 0), HH - 1);
        int r1 = min(max(py,     0), HH - 1);
        int c0 = min(max(px - 1, 0), WW - 1);
        int c1 = min(max(px,     0), WW - 1);
        bool road = (hd[r0 * WW + c0] == 1.0f) || (hd[r0 * WW + c1] == 1.0f) ||
                    (hd[r1 * WW + c0] == 1.0f) || (hd[r1 * WW + c1] == 1.0f);
        float d2on  = (float)g_on[n];
        float d2off = (float)g_off[n];
        const float K1 = 21.7f;
        const float LN2_OVER_K2 = 0.69314718055994531f / 40.0f;
        loss = road ? expf(sqrtf(d2off) * LN2_OVER_K2)
                    : expf(-d2on / K1);
    }

    __shared__ float s[128];
    s[n] = loss;
    __syncthreads();
    #pragma unroll
    for (int st = 64; st > 0; st >>= 1) {
        if (n < st) s[n] += s[n + st];
        __syncthreads();
    }
    if (n == 0) out[0] = s[0] * (1.0f / (float)NPTS);
}

extern "C" void kernel_launch(void* const* d_in, const int* in_sizes, int n_in,
                              void* d_out, int out_size) {
    const float* hd  = (const float*)d_in[0];
    const int* pred  = (const int*)d_in[1];
    float* out       = (float*)d_out;

    // 32768 words, one per warp: 4096 blocks x 256 threads (8 warps)
    bitpack_kernel<<<4096, 256>>>(hd);
    // one block per point
    search_kernel<<<NPTS, 256>>>(pred);
    // single small block for loss + mean
    finalize_kernel<<<1, 128>>>(hd, pred, out);
}

// round 3
// speedup vs baseline: 1.6012x; 1.6012x over previous
#include <cuda_runtime.h>

#define HH 1024
#define WW 1024
#define NPTS 128
#define WPR 32            // 32-bit words per row (1024/32)
#define SENTINEL_D 2048   // > max real 1D distance (1023)

// Bitmap stored COLUMN-MAJOR over word-columns: g_bits[wc*HH + r]
// so the per-point row sweep in search_kernel is coalesced (consecutive r).
__device__ unsigned int g_bits[WPR * HH];
__device__ int g_on[NPTS];
__device__ int g_off[NPTS];

// ---------------------------------------------------------------------------
// Kernel 1: bitpack, 8 words per warp for MLP=8.
// Warp gw covers row r = gw>>2, column chunk = (gw&3)*256.
// Lane loads 8 floats at stride 32 (each load coalesced across the warp),
// all issued before the ballots -> 8 outstanding loads per thread.
// ---------------------------------------------------------------------------
__global__ void bitpack_kernel(const float* __restrict__ hd) {
    int gw   = (blockIdx.x * blockDim.x + threadIdx.x) >> 5;   // 4096 warps
    int lane = threadIdx.x & 31;
    int r     = gw >> 2;          // 4 warps per row
    int chunk = gw & 3;           // 256-column chunk
    const float* base = hd + r * WW + (chunk << 8) + lane;

    float v0 = base[0];
    float v1 = base[32];
    float v2 = base[64];
    float v3 = base[96];
    float v4 = base[128];
    float v5 = base[160];
    float v6 = base[192];
    float v7 = base[224];

    unsigned int w0 = __ballot_sync(0xFFFFFFFFu, v0 != 0.0f);
    unsigned int w1 = __ballot_sync(0xFFFFFFFFu, v1 != 0.0f);
    unsigned int w2 = __ballot_sync(0xFFFFFFFFu, v2 != 0.0f);
    unsigned int w3 = __ballot_sync(0xFFFFFFFFu, v3 != 0.0f);
    unsigned int w4 = __ballot_sync(0xFFFFFFFFu, v4 != 0.0f);
    unsigned int w5 = __ballot_sync(0xFFFFFFFFu, v5 != 0.0f);
    unsigned int w6 = __ballot_sync(0xFFFFFFFFu, v6 != 0.0f);
    unsigned int w7 = __ballot_sync(0xFFFFFFFFu, v7 != 0.0f);

    unsigned int ws;
    switch (lane) {
        case 0: ws = w0; break; case 1: ws = w1; break;
        case 2: ws = w2; break; case 3: ws = w3; break;
        case 4: ws = w4; break; case 5: ws = w5; break;
        case 6: ws = w6; break; default: ws = w7; break;
    }
    if (lane < 8) {
        int wc = (chunk << 3) + lane;
        g_bits[wc * HH + r] = ws;
    }
}

// Nearest set-bit distance from query column q (= wc0*32+bit0) to any set bit
// in word m at word index w. Returns sentinel if m == 0.
__device__ __forceinline__ int nearest_in_word(unsigned int m, int w, int wc0, int bit0) {
    if (m == 0u) return SENTINEL_D;
    if (w == wc0) {
        unsigned int maskLE = (bit0 == 31) ? 0xFFFFFFFFu : ((2u << bit0) - 1u);
        unsigned int lo = m & maskLE;
        unsigned int hi = m & ~maskLE;
        int d = SENTINEL_D;
        if (lo) d = bit0 - (31 - __clz(lo));
        if (hi) { int d2 = (__ffs(hi) - 1) - bit0; d = min(d, d2); }
        return d;
    } else if (w > wc0) {
        return (w << 5) + (__ffs(m) - 1) - ((wc0 << 5) + bit0);
    } else {
        return ((wc0 << 5) + bit0) - ((w << 5) + (31 - __clz(m)));
    }
}

// ---------------------------------------------------------------------------
// Kernel 2: per-point separable search. Block n = point n, thread = one row.
// Rings 0 and +-1 are loaded up-front as independent (coalesced) L2 loads;
// extension beyond ring 1 is statistically rare at 30%/70% bit densities.
// Block-reduce min via REDUX + one shared pass. No atomics.
// ---------------------------------------------------------------------------
__global__ void search_kernel(const int* __restrict__ pred) {
    int n  = blockIdx.x;
    int pr = pred[2 * n];       // compared against rows
    int pc = pred[2 * n + 1];   // compared against cols
    int r  = threadIdx.x;       // 1024 threads = 1024 rows

    int wc0  = pc >> 5;
    int bit0 = pc & 31;
    int q32  = (wc0 << 5) + bit0;

    // Pre-issue ring 0 and ring 1 loads (independent, coalesced across warp).
    unsigned int m0 = g_bits[wc0 * HH + r];
    bool hasL = (wc0 - 1 >= 0);
    bool hasR = (wc0 + 1 < WPR);
    unsigned int mL = hasL ? g_bits[(wc0 - 1) * HH + r] : 0u;
    unsigned int mR = hasR ? g_bits[(wc0 + 1) * HH + r] : 0u;

    int don  = nearest_in_word(m0,  wc0, wc0, bit0);
    int doff = nearest_in_word(~m0, wc0, wc0, bit0);
    if (hasL) {
        don  = min(don,  nearest_in_word(mL,  wc0 - 1, wc0, bit0));
        doff = min(doff, nearest_in_word(~mL, wc0 - 1, wc0, bit0));
    }
    if (hasR) {
        don  = min(don,  nearest_in_word(mR,  wc0 + 1, wc0, bit0));
        doff = min(doff, nearest_in_word(~mR, wc0 + 1, wc0, bit0));
    }

    // Lower bound on any distance achievable in ring >= 2.
    {
        int cminR = (wc0 + 2 < WPR) ? ((wc0 + 2) << 5) - q32        : SENTINEL_D;
        int cminL = (wc0 - 2 >= 0)  ? q32 - (((wc0 - 2) << 5) + 31) : SENTINEL_D;
        int nextmin = min(cminR, cminL);
        if (don > nextmin || doff > nextmin) {
            #pragma unroll 1
            for (int k = 2; k < WPR + 1; k++) {
                int wr = wc0 + k;
                int wl = wc0 - k;
                if (wr < WPR) {
                    unsigned int m = g_bits[wr * HH + r];
                    don  = min(don,  nearest_in_word(m,  wr, wc0, bit0));
                    doff = min(doff, nearest_in_word(~m, wr, wc0, bit0));
                }
                if (wl >= 0) {
                    unsigned int m = g_bits[wl * HH + r];
                    don  = min(don,  nearest_in_word(m,  wl, wc0, bit0));
                    doff = min(doff, nearest_in_word(~m, wl, wc0, bit0));
                }
                int cR = (wr + 1 < WPR) ? ((wr + 1) << 5) - q32        : SENTINEL_D;
                int cL = (wl - 1 >= 0)  ? q32 - (((wl - 1) << 5) + 31) : SENTINEL_D;
                int nm = min(cR, cL);
                if (don <= nm && doff <= nm) break;
            }
        }
    }
    don  = min(don,  SENTINEL_D);
    doff = min(doff, SENTINEL_D);

    int dr  = r - pr;
    int dr2 = dr * dr;
    int best_on  = dr2 + don * don;
    int best_off = dr2 + doff * doff;

    // Warp-level min, then cross-warp via shared.
    best_on  = __reduce_min_sync(0xFFFFFFFFu, best_on);
    best_off = __reduce_min_sync(0xFFFFFFFFu, best_off);

    __shared__ int s_on[32];
    __shared__ int s_off[32];
    int wid  = threadIdx.x >> 5;
    int lane = threadIdx.x & 31;
    if (lane == 0) { s_on[wid] = best_on; s_off[wid] = best_off; }
    __syncthreads();
    if (wid == 0) {
        int a = s_on[lane];
        int b = s_off[lane];
        a = __reduce_min_sync(0xFFFFFFFFu, a);
        b = __reduce_min_sync(0xFFFFFFFFu, b);
        if (lane == 0) { g_on[n] = a; g_off[n] = b; }
    }
}

// ---------------------------------------------------------------------------
// Kernel 3: per-point loss + mean. Replicates the reference's swapped-index
// neighbor lookup (hd_map[py-1..py, px-1..px]) with JAX-style clamping.
// ---------------------------------------------------------------------------
__global__ void finalize_kernel(const float* __restrict__ hd,
                                const int* __restrict__ pred,
                                float* __restrict__ out) {
    int n = threadIdx.x;   // 128 threads
    int px = pred[2 * n];
    int py = pred[2 * n + 1];
    bool outside_frame = (px < 0) || (px > HH) || (py < 0) || (py > WW);

    float loss = 0.0f;
    if (!outside_frame) {
        int r0 = min(max(py - 1, 0), HH - 1);
        int r1 = min(max(py,     0), HH - 1);
        int c0 = min(max(px - 1, 0), WW - 1);
        int c1 = min(max(px,     0), WW - 1);
        bool road = (hd[r0 * WW + c0] == 1.0f) || (hd[r0 * WW + c1] == 1.0f) ||
                    (hd[r1 * WW + c0] == 1.0f) || (hd[r1 * WW + c1] == 1.0f);
        float d2on  = (float)g_on[n];
        float d2off = (float)g_off[n];
        const float K1 = 21.7f;
        const float LN2_OVER_K2 = 0.69314718055994531f / 40.0f;
        loss = road ? expf(sqrtf(d2off) * LN2_OVER_K2)
                    : expf(-d2on / K1);
    }

    __shared__ float s[128];
    s[n] = loss;
    __syncthreads();
    #pragma unroll
    for (int st = 64; st > 0; st >>= 1) {
        if (n < st) s[n] += s[n + st];
        __syncthreads();
    }
    if (n == 0) out[0] = s[0] * (1.0f / (float)NPTS);
}

extern "C" void kernel_launch(void* const* d_in, const int* in_sizes, int n_in,
                              void* d_out, int out_size) {
    const float* hd  = (const float*)d_in[0];
    const int* pred  = (const int*)d_in[1];
    float* out       = (float*)d_out;

    // 4096 warps x 8 words each = 32768 words
    bitpack_kernel<<<512, 256>>>(hd);
    // one block per point, one thread per row
    search_kernel<<<NPTS, 1024>>>(pred);
    finalize_kernel<<<1, 128>>>(hd, pred, out);
}